// round 11
// baseline (speedup 1.0000x reference)
#include <cuda_runtime.h>

// ProbAttention (Informer ProbSparse) for B=2, L=4096, H=8, D=64, sample_k = n_top = 45.

#define Bb   2
#define Ll   4096
#define Hh   8
#define Dd   64
#define SSK  45          // sample_k == n_top
#define BH   (Bb*Hh)     // 16
#define NC   16          // kv chunks in phase 3 (k3)
#define CK   256         // keys per chunk in k3
#define SST  257         // padded ss row stride (floats)
#define KC   512         // keys per chunk in k1
#define NKC  8           // Ll / KC

typedef unsigned long long ull;

// ---- scratch (static device globals: no allocation allowed) ----
__device__ int    g_idx_is64;
__device__ int    g_bidx[Ll * SSK];      // sample indices bucketed by key-chunk
__device__ int    g_boff[Ll * (NKC + 1)];
__device__ float  g_pM[BH * NKC * Ll];   // per-chunk partial max
__device__ float  g_pS[BH * NKC * Ll];   // per-chunk partial sum
__device__ float  g_M[BH * Ll];
__device__ int    g_top[BH * SSK];
__device__ float  g_pmax[BH * NC * SSK];
__device__ float  g_psum[BH * NC * SSK];
__device__ float4 g_pout[BH * NC * SSK * (Dd / 4)];

// ---- f32x2 packed-FMA helpers ----
__device__ __forceinline__ ull fma2(ull a, ull b, ull c) {
    ull d;
    asm("fma.rn.f32x2 %0, %1, %2, %3;" : "=l"(d) : "l"(a), "l"(b), "l"(c));
    return d;
}
__device__ __forceinline__ ull pack2(float x, float y) {
    ull r;
    asm("mov.b64 %0, {%1, %2};" : "=l"(r) : "f"(x), "f"(y));
    return r;
}
__device__ __forceinline__ void unpack2(ull v, float& x, float& y) {
    asm("mov.b64 {%0, %1}, %2;" : "=f"(x), "=f"(y) : "l"(v));
}

// ---------------- K0: zero output + detect index dtype ----------------
__global__ void k0_zero(float4* __restrict__ out4, int n4,
                        const unsigned* __restrict__ idxsrc) {
    if (blockIdx.x == 0) {
        __shared__ int nz;
        if (threadIdx.x == 0) nz = 0;
        __syncthreads();
        if (threadIdx.x < 128) {
            unsigned v = idxsrc[threadIdx.x * 2 + 1];
            if (v != 0u) atomicAdd(&nz, 1);
        }
        __syncthreads();
        if (threadIdx.x == 0) g_idx_is64 = (nz == 0) ? 1 : 0;
    }
    int i = blockIdx.x * 256 + threadIdx.x;
    if (i < n4) out4[i] = make_float4(0.f, 0.f, 0.f, 0.f);
}

// ---------------- KB: bucket sample indices by key-chunk (warp per l) ----------------
__global__ __launch_bounds__(256) void kb_bucket(const void* __restrict__ idxsrc) {
    int l    = blockIdx.x * 8 + (threadIdx.x >> 5);
    int lane = threadIdx.x & 31;
    const int is64 = g_idx_is64;
    const long long* p64 = (const long long*)idxsrc + (size_t)l * SSK;
    const int*       p32 = (const int*)idxsrc + (size_t)l * SSK;

    int s0 = is64 ? (int)p64[lane] : p32[lane];
    bool has1 = lane < (SSK - 32);               // 13 extra lanes
    int s1 = has1 ? (is64 ? (int)p64[lane + 32] : p32[lane + 32]) : 0;
    int c0 = s0 >> 9;
    int c1 = has1 ? (s1 >> 9) : -1;

    unsigned lmask = (1u << lane) - 1u;
    int base = 0;
    #pragma unroll
    for (int c = 0; c < NKC; c++) {
        unsigned m0 = __ballot_sync(0xffffffffu, c0 == c);
        unsigned m1 = __ballot_sync(0xffffffffu, c1 == c);
        if (lane == 0) g_boff[l * (NKC + 1) + c] = base;
        if (c0 == c) g_bidx[l * SSK + base + __popc(m0 & lmask)] = s0;
        if (c1 == c) g_bidx[l * SSK + base + __popc(m0) + __popc(m1 & lmask)] = s1;
        base += __popc(m0) + __popc(m1);
    }
    if (lane == 0) g_boff[l * (NKC + 1) + NKC] = SSK;
}

// ---------------- K1: chunked sampled scoring ----------------
// Grid (NKC, BH). CTA stages its 512-key x 64d chunk once in smem (128KB),
// then streams all l: 16-lane half per l scores only in-chunk samples.
#define K1C_SMEM (KC * Dd * 4)
__global__ __launch_bounds__(512) void k1_chunk(const float4* __restrict__ q4,
                                                const float4* __restrict__ k4) {
    int kc = blockIdx.x;
    int bh = blockIdx.y;
    int b = bh >> 3, h = bh & 7;
    int tid = threadIdx.x;

    extern __shared__ float4 ks4[];   // [KC][16]
    for (int i = tid; i < KC * 16; i += 512) {
        int row = i >> 4, c4 = i & 15;
        ks4[row * 16 + c4] =
            k4[((size_t)(b * Ll + kc * KC + row) * Hh + h) * 16 + c4];
    }
    __syncthreads();

    int wid = tid >> 5, lane = tid & 31;
    int half = lane >> 4, lh = lane & 15;
    unsigned hmask = half ? 0xffff0000u : 0x0000ffffu;

    for (int l2 = wid; l2 < Ll / 2; l2 += 16) {
        int l = l2 * 2 + half;
        float4 qv = q4[((size_t)(b * Ll + l) * Hh + h) * 16 + lh];
        int o0 = g_boff[l * (NKC + 1) + kc];
        int o1 = g_boff[l * (NKC + 1) + kc + 1];
        float mx = -1e30f, sm = 0.f;
        for (int s = o0; s < o1; s++) {
            int kidx = g_bidx[l * SSK + s] - kc * KC;
            float4 kv = ks4[kidx * 16 + lh];
            float p = qv.x*kv.x + qv.y*kv.y + qv.z*kv.z + qv.w*kv.w;
            p += __shfl_xor_sync(hmask, p, 8);
            p += __shfl_xor_sync(hmask, p, 4);
            p += __shfl_xor_sync(hmask, p, 2);
            p += __shfl_xor_sync(hmask, p, 1);
            mx = fmaxf(mx, p);
            sm += p;
        }
        if (lh == 0) {
            g_pM[(bh * NKC + kc) * Ll + l] = mx;
            g_pS[(bh * NKC + kc) * Ll + l] = sm;
        }
    }
}

// ---------------- K1b: combine chunk partials into M ----------------
__global__ __launch_bounds__(256) void k1b_combine() {
    int l  = blockIdx.x * 256 + threadIdx.x;
    int bh = blockIdx.y;
    float mx = -1e30f, sm = 0.f;
    #pragma unroll
    for (int kc = 0; kc < NKC; kc++) {
        mx = fmaxf(mx, g_pM[(bh * NKC + kc) * Ll + l]);
        sm += g_pS[(bh * NKC + kc) * Ll + l];
    }
    g_M[bh * Ll + l] = mx - sm * (1.0f / (float)Ll);
}

// ---------------- K2: top-45 per (b,h) via 4-round radix select ----------------
__global__ __launch_bounds__(256) void k2_topk() {
    int bh  = blockIdx.x;
    int tid = threadIdx.x;
    int wid = tid >> 5, lane = tid & 31;

    __shared__ unsigned hist[256];
    __shared__ unsigned warptot[8];
    __shared__ unsigned sh_pivot, sh_above;
    __shared__ int n_gt, n_eq;

    unsigned key[16];
    #pragma unroll
    for (int i = 0; i < 16; i++) {
        unsigned u = __float_as_uint(g_M[bh * Ll + i * 256 + tid]);
        key[i] = (u & 0x80000000u) ? ~u : (u | 0x80000000u);
    }

    unsigned prefix = 0, pmask = 0;
    int need = SSK;

    #pragma unroll
    for (int round = 0; round < 4; round++) {
        int shift = 24 - round * 8;
        hist[tid] = 0;
        if (tid == 0) { n_gt = 0; n_eq = 0; }
        __syncthreads();
        #pragma unroll
        for (int i = 0; i < 16; i++)
            if ((key[i] & pmask) == prefix)
                atomicAdd(&hist[(key[i] >> shift) & 255u], 1u);
        __syncthreads();

        unsigned x = hist[tid];
        unsigned s = x;
        #pragma unroll
        for (int o = 1; o < 32; o <<= 1) {
            unsigned y = __shfl_down_sync(0xffffffffu, s, o);
            if (lane + o < 32) s += y;
        }
        unsigned wt = __shfl_sync(0xffffffffu, s, 0);
        if (lane == 0) warptot[wid] = wt;
        __syncthreads();
        unsigned hs = 0;
        #pragma unroll
        for (int w2 = 0; w2 < 8; w2++)
            if (w2 > wid) hs += warptot[w2];
        unsigned S = s + hs;
        unsigned above = S - x;
        if ((int)S >= need && (int)above < need) {
            sh_pivot = (unsigned)tid;
            sh_above = above;
        }
        __syncthreads();
        prefix |= sh_pivot << shift;
        pmask  |= 0xffu << shift;
        need   -= (int)sh_above;
        __syncthreads();
    }

    int base = bh * SSK;
    #pragma unroll
    for (int i = 0; i < 16; i++)
        if (key[i] > prefix) {
            int p = atomicAdd(&n_gt, 1);
            g_top[base + p] = i * 256 + tid;
        }
    __syncthreads();
    int gt = n_gt;
    #pragma unroll
    for (int i = 0; i < 16; i++)
        if (key[i] == prefix) {
            int e = atomicAdd(&n_eq, 1);
            if (e < need) g_top[base + gt + e] = i * 256 + tid;
        }
}

// ---------------- K3: split-KV sparse attention partials ----------------
#define K3T   256
#define QS2F  (23 * 128)
#define KVF   (CK * 9 * 4)
#define K3_SMEM ((QS2F + KVF + SSK * SST) * 4 + 256)

__global__ __launch_bounds__(K3T, 2) void k3_attn(const float4* __restrict__ q4,
                                                  const float4* __restrict__ k4g,
                                                  const float4* __restrict__ v4g) {
    int c  = blockIdx.x;
    int bh = blockIdx.y;
    int b = bh >> 3, h = bh & 7;
    int tid = threadIdx.x;

    extern __shared__ float smem[];
    float* qs2f = smem;
    float* kv   = qs2f + QS2F;
    float* ss   = kv + KVF;
    int*   tops = (int*)(ss + SSK * SST);
    float4*           kv4 = (float4*)kv;
    const ulonglong2* kvU = (const ulonglong2*)kv;
    const ulonglong2* qsU = (const ulonglong2*)qs2f;

    if (tid < SSK) tops[tid] = g_top[bh * SSK + tid];
    __syncthreads();

    for (int i = tid; i < 46 * 16; i += K3T) {
        int u = i >> 4, c4 = i & 15;
        float4 qv = (u < SSK)
            ? q4[((size_t)(b * Ll + tops[u]) * Hh + h) * (Dd / 4) + c4]
            : make_float4(0.f, 0.f, 0.f, 0.f);
        float* dst = qs2f + ((u >> 1) * 128 + 8 * c4) + (u & 1);
        dst[0] = qv.x; dst[2] = qv.y; dst[4] = qv.z; dst[6] = qv.w;
    }

    int k0 = c * CK;
    int j = tid;

    ull acc[23];
    #pragma unroll
    for (int i = 0; i < 23; i++) acc[i] = 0ull;

    #pragma unroll 1
    for (int cc = 0; cc < 2; cc++) {
        __syncthreads();
        for (int i = tid; i < CK * 8; i += K3T) {
            int row = i >> 3, dc = i & 7;
            kv4[row * 9 + dc] =
                k4g[((size_t)(b * Ll + k0 + row) * Hh + h) * 16 + cc * 8 + dc];
        }
        __syncthreads();
        #pragma unroll 1
        for (int dc = 0; dc < 8; dc++) {
            float4 kr = kv4[j * 9 + dc];
            ull kk0 = pack2(kr.x, kr.x);
            ull kk1 = pack2(kr.y, kr.y);
            ull kk2 = pack2(kr.z, kr.z);
            ull kk3 = pack2(kr.w, kr.w);
            int dcg = cc * 8 + dc;
            #pragma unroll
            for (int i = 0; i < 23; i++) {
                ulonglong2 qA = qsU[i * 32 + dcg * 2];
                ulonglong2 qB = qsU[i * 32 + dcg * 2 + 1];
                acc[i] = fma2(qA.x, kk0, acc[i]);
                acc[i] = fma2(qA.y, kk1, acc[i]);
                acc[i] = fma2(qB.x, kk2, acc[i]);
                acc[i] = fma2(qB.y, kk3, acc[i]);
            }
        }
    }
    #pragma unroll
    for (int i = 0; i < 23; i++) {
        float lo, hi;
        unpack2(acc[i], lo, hi);
        ss[(2 * i) * SST + j] = lo;
        if (2 * i + 1 < SSK) ss[(2 * i + 1) * SST + j] = hi;
    }
    __syncthreads();

    int wid = tid >> 5, lane = tid & 31;
    for (int u = wid; u < SSK; u += 8) {
        float x[8];
        float mxv = -1e30f;
        #pragma unroll
        for (int t = 0; t < 8; t++) { x[t] = ss[u * SST + lane + t * 32]; mxv = fmaxf(mxv, x[t]); }
        #pragma unroll
        for (int o = 16; o; o >>= 1) mxv = fmaxf(mxv, __shfl_xor_sync(0xffffffffu, mxv, o));
        float sum = 0.f;
        #pragma unroll
        for (int t = 0; t < 8; t++) { float p = __expf(0.125f * (x[t] - mxv)); x[t] = p; sum += p; }
        #pragma unroll
        for (int o = 16; o; o >>= 1) sum += __shfl_xor_sync(0xffffffffu, sum, o);
        #pragma unroll
        for (int t = 0; t < 8; t++) ss[u * SST + lane + t * 32] = x[t];
        if (lane == 0) {
            g_pmax[(bh * NC + c) * SSK + u] = 0.125f * mxv;
            g_psum[(bh * NC + c) * SSK + u] = sum;
        }
    }

    int d4 = tid & 15, ug = tid >> 4;
    int u0 = ug * 3;
    ull a0l = 0, a0h = 0, a1l = 0, a1h = 0, a2l = 0, a2h = 0;

    #pragma unroll 1
    for (int vc = 0; vc < 2; vc++) {
        __syncthreads();
        for (int i = tid; i < 128 * 16; i += K3T) {
            int row = i >> 4, c4 = i & 15;
            kv4[row * 17 + c4] =
                v4g[((size_t)(b * Ll + k0 + vc * 128 + row) * Hh + h) * 16 + c4];
        }
        __syncthreads();
        if (ug < 15) {
            #pragma unroll 4
            for (int jj = 0; jj < 128; jj++) {
                ulonglong2 vv = kvU[jj * 17 + d4];
                int jg = vc * 128 + jj;
                float p0 = ss[u0 * SST + jg];
                float p1 = ss[(u0 + 1) * SST + jg];
                float p2 = ss[(u0 + 2) * SST + jg];
                ull b0 = pack2(p0, p0), b1 = pack2(p1, p1), b2 = pack2(p2, p2);
                a0l = fma2(b0, vv.x, a0l);  a0h = fma2(b0, vv.y, a0h);
                a1l = fma2(b1, vv.x, a1l);  a1h = fma2(b1, vv.y, a1h);
                a2l = fma2(b2, vv.x, a2l);  a2h = fma2(b2, vv.y, a2h);
            }
        }
    }
    if (ug < 15) {
        ulonglong2* po = (ulonglong2*)g_pout;
        size_t baseo = ((size_t)(bh * NC + c) * SSK) * 16 + d4;
        po[baseo + (size_t)u0 * 16]       = make_ulonglong2(a0l, a0h);
        po[baseo + (size_t)(u0 + 1) * 16] = make_ulonglong2(a1l, a1h);
        po[baseo + (size_t)(u0 + 2) * 16] = make_ulonglong2(a2l, a2h);
    }
}

// ---------------- K4: combine partials + scatter ----------------
__global__ __launch_bounds__(256) void k4_combine(float4* __restrict__ out4) {
    int bh = blockIdx.x;
    int b = bh >> 3, h = bh & 7;
    for (int i = threadIdx.x; i < SSK * 16; i += 256) {
        int u = i >> 4, d4 = i & 15;
        float gm = -1e30f;
        #pragma unroll
        for (int cc = 0; cc < NC; cc++)
            gm = fmaxf(gm, g_pmax[(bh * NC + cc) * SSK + u]);
        float denom = 0.f;
        float4 a = make_float4(0.f, 0.f, 0.f, 0.f);
        #pragma unroll
        for (int cc = 0; cc < NC; cc++) {
            float w = __expf(g_pmax[(bh * NC + cc) * SSK + u] - gm);
            denom += g_psum[(bh * NC + cc) * SSK + u] * w;
            float4 po = g_pout[((bh * NC + cc) * SSK + u) * 16 + d4];
            a.x += w * po.x; a.y += w * po.y; a.z += w * po.z; a.w += w * po.w;
        }
        float inv = 1.0f / denom;
        a.x *= inv; a.y *= inv; a.z *= inv; a.w *= inv;
        int lsel = g_top[bh * SSK + u];
        out4[((size_t)(b * Ll + lsel) * Hh + h) * 16 + d4] = a;
    }
}

// ---------------- launch ----------------
extern "C" void kernel_launch(void* const* d_in, const int* in_sizes, int n_in,
                              void* d_out, int out_size) {
    const float4* q4 = (const float4*)d_in[0];
    const float4* k4 = (const float4*)d_in[1];
    const float4* v4 = (const float4*)d_in[2];
    const void* idxp = d_in[n_in - 1];
    for (int i = 0; i < n_in; i++)
        if (in_sizes[i] == Ll * SSK) idxp = d_in[i];
    float4* out4 = (float4*)d_out;

    cudaFuncSetAttribute(k1_chunk, cudaFuncAttributeMaxDynamicSharedMemorySize, K1C_SMEM);
    cudaFuncSetAttribute(k3_attn, cudaFuncAttributeMaxDynamicSharedMemorySize, K3_SMEM);

    int n4 = out_size / 4;
    k0_zero<<<(n4 + 255) / 256, 256>>>(out4, n4, (const unsigned*)idxp);
    kb_bucket<<<Ll / 8, 256>>>(idxp);
    k1_chunk<<<dim3(NKC, BH), 512, K1C_SMEM>>>(q4, k4);
    k1b_combine<<<dim3(Ll / 256, BH), 256>>>();
    k2_topk<<<BH, 256>>>();
    k3_attn<<<dim3(NC, BH), K3T, K3_SMEM>>>(q4, k4, v4);
    k4_combine<<<BH, 256>>>(out4);
}

// round 13
// speedup vs baseline: 2.2653x; 2.2653x over previous
#include <cuda_runtime.h>

// ProbAttention (Informer ProbSparse) for B=2, L=4096, H=8, D=64, sample_k = n_top = 45.

#define Bb   2
#define Ll   4096
#define Hh   8
#define Dd   64
#define SSK  45          // sample_k == n_top
#define BH   (Bb*Hh)     // 16
#define NC   16          // kv chunks in phase 3
#define CK   256         // keys per chunk in k3
#define SST  257         // padded ss row stride (floats)

typedef unsigned long long ull;

// ---- scratch (static device globals: no allocation allowed) ----
__device__ int    g_idx_is64;
__device__ float  g_M[BH * Ll];
__device__ int    g_top[BH * SSK];
__device__ float  g_pmax[BH * NC * SSK];
__device__ float  g_psum[BH * NC * SSK];
__device__ float4 g_pout[BH * NC * SSK * (Dd / 4)];
__device__ int    g_cnt[BH];             // k3 completion counters (reset each launch)

// ---- f32x2 packed-FMA helpers ----
__device__ __forceinline__ ull fma2(ull a, ull b, ull c) {
    ull d;
    asm("fma.rn.f32x2 %0, %1, %2, %3;" : "=l"(d) : "l"(a), "l"(b), "l"(c));
    return d;
}
__device__ __forceinline__ ull pack2(float x, float y) {
    ull r;
    asm("mov.b64 %0, {%1, %2};" : "=l"(r) : "f"(x), "f"(y));
    return r;
}
__device__ __forceinline__ void unpack2(ull v, float& x, float& y) {
    asm("mov.b64 {%0, %1}, %2;" : "=f"(x), "=f"(y) : "l"(v));
}

// ---------------- K0: zero output + detect index dtype + reset counters ----------------
__global__ void k0_zero(float4* __restrict__ out4, int n4,
                        const unsigned* __restrict__ idxsrc) {
    if (blockIdx.x == 0) {
        __shared__ int nz;
        if (threadIdx.x == 0) nz = 0;
        __syncthreads();
        if (threadIdx.x < 128) {
            unsigned v = idxsrc[threadIdx.x * 2 + 1];
            if (v != 0u) atomicAdd(&nz, 1);
        }
        __syncthreads();
        if (threadIdx.x == 0) g_idx_is64 = (nz == 0) ? 1 : 0;
        if (threadIdx.x < BH) g_cnt[threadIdx.x] = 0;
    }
    int i = blockIdx.x * 256 + threadIdx.x;
    if (i < n4) out4[i] = make_float4(0.f, 0.f, 0.f, 0.f);
}

// ---------------- K1: sampled scores M ----------------
// One warp per (b,l); 8 heads at once; fully coalesced 512B loads per step.
__global__ __launch_bounds__(256) void k1_score(const float4* __restrict__ q4,
                                                const float4* __restrict__ k4,
                                                const void* __restrict__ idxsrc) {
    int w    = blockIdx.x * 8 + (threadIdx.x >> 5);
    int lane = threadIdx.x & 31;
    int b = w >> 12;
    int l = w & (Ll - 1);

    const float4* qp = q4 + (size_t)(b * Ll + l) * (Hh * Dd / 4);
    float4 qv[4];
    #pragma unroll
    for (int t = 0; t < 4; t++) qv[t] = qp[t * 32 + lane];

    float mx[4] = {-1e30f, -1e30f, -1e30f, -1e30f};
    float sm[4] = {0.f, 0.f, 0.f, 0.f};

    const int is64 = g_idx_is64;
    const long long* ip64 = (const long long*)idxsrc + (size_t)l * SSK;
    const int*       ip32 = (const int*)idxsrc + (size_t)l * SSK;

    #pragma unroll 2
    for (int s = 0; s < SSK; s++) {
        int idx = is64 ? (int)ip64[s] : ip32[s];
        const float4* kp = k4 + (size_t)(b * Ll + idx) * (Hh * Dd / 4);
        #pragma unroll
        for (int t = 0; t < 4; t++) {
            float4 kv = kp[t * 32 + lane];
            float p = qv[t].x*kv.x + qv[t].y*kv.y + qv[t].z*kv.z + qv[t].w*kv.w;
            p += __shfl_xor_sync(0xffffffffu, p, 8);
            p += __shfl_xor_sync(0xffffffffu, p, 4);
            p += __shfl_xor_sync(0xffffffffu, p, 2);
            p += __shfl_xor_sync(0xffffffffu, p, 1);
            mx[t] = fmaxf(mx[t], p);
            sm[t] += p;
        }
    }
    if ((lane & 15) == 0) {
        int half = lane >> 4;
        #pragma unroll
        for (int t = 0; t < 4; t++) {
            int h = 2 * t + half;
            g_M[(b * Hh + h) * Ll + l] = mx[t] - sm[t] * (1.0f / (float)Ll);
        }
    }
}

// ---------------- K2: top-45 per (b,h) via 4-round radix select ----------------
__global__ __launch_bounds__(256) void k2_topk() {
    int bh  = blockIdx.x;
    int tid = threadIdx.x;
    int wid = tid >> 5, lane = tid & 31;

    __shared__ unsigned hist[256];
    __shared__ unsigned warptot[8];
    __shared__ unsigned sh_pivot, sh_above;
    __shared__ int n_gt, n_eq;

    unsigned key[16];
    #pragma unroll
    for (int i = 0; i < 16; i++) {
        unsigned u = __float_as_uint(g_M[bh * Ll + i * 256 + tid]);
        key[i] = (u & 0x80000000u) ? ~u : (u | 0x80000000u);
    }

    unsigned prefix = 0, pmask = 0;
    int need = SSK;

    #pragma unroll
    for (int round = 0; round < 4; round++) {
        int shift = 24 - round * 8;
        hist[tid] = 0;
        if (tid == 0) { n_gt = 0; n_eq = 0; }
        __syncthreads();
        #pragma unroll
        for (int i = 0; i < 16; i++)
            if ((key[i] & pmask) == prefix)
                atomicAdd(&hist[(key[i] >> shift) & 255u], 1u);
        __syncthreads();

        unsigned x = hist[tid];
        unsigned s = x;
        #pragma unroll
        for (int o = 1; o < 32; o <<= 1) {
            unsigned y = __shfl_down_sync(0xffffffffu, s, o);
            if (lane + o < 32) s += y;
        }
        unsigned wt = __shfl_sync(0xffffffffu, s, 0);
        if (lane == 0) warptot[wid] = wt;
        __syncthreads();
        unsigned hs = 0;
        #pragma unroll
        for (int w2 = 0; w2 < 8; w2++)
            if (w2 > wid) hs += warptot[w2];
        unsigned S = s + hs;
        unsigned above = S - x;
        if ((int)S >= need && (int)above < need) {
            sh_pivot = (unsigned)tid;
            sh_above = above;
        }
        __syncthreads();
        prefix |= sh_pivot << shift;
        pmask  |= 0xffu << shift;
        need   -= (int)sh_above;
        __syncthreads();
    }

    int base = bh * SSK;
    #pragma unroll
    for (int i = 0; i < 16; i++)
        if (key[i] > prefix) {
            int p = atomicAdd(&n_gt, 1);
            g_top[base + p] = i * 256 + tid;
        }
    __syncthreads();
    int gt = n_gt;
    #pragma unroll
    for (int i = 0; i < 16; i++)
        if (key[i] == prefix) {
            int e = atomicAdd(&n_eq, 1);
            if (e < need) g_top[base + gt + e] = i * 256 + tid;
        }
}

// ---------------- K3: split-KV sparse attention + fused combine ----------------
#define K3T   256
#define QS2F  (23 * 128)
#define KVF   (CK * 9 * 4)
#define K3_SMEM ((QS2F + KVF + SSK * SST) * 4 + 256)

__global__ __launch_bounds__(K3T, 2) void k3_attn(const float4* __restrict__ q4,
                                                  const float4* __restrict__ k4g,
                                                  const float4* __restrict__ v4g,
                                                  float4* __restrict__ out4) {
    int c  = blockIdx.x;
    int bh = blockIdx.y;
    int b = bh >> 3, h = bh & 7;
    int tid = threadIdx.x;

    extern __shared__ float smem[];
    float* qs2f = smem;
    float* kv   = qs2f + QS2F;
    float* ss   = kv + KVF;
    int*   tops = (int*)(ss + SSK * SST);
    float4*           kv4 = (float4*)kv;
    const ulonglong2* kvU = (const ulonglong2*)kv;
    const ulonglong2* qsU = (const ulonglong2*)qs2f;

    if (tid < SSK) tops[tid] = g_top[bh * SSK + tid];
    __syncthreads();

    // stage Q in u-pair-packed layout
    for (int i = tid; i < 46 * 16; i += K3T) {
        int u = i >> 4, c4 = i & 15;
        float4 qv = (u < SSK)
            ? q4[((size_t)(b * Ll + tops[u]) * Hh + h) * (Dd / 4) + c4]
            : make_float4(0.f, 0.f, 0.f, 0.f);
        float* dst = qs2f + ((u >> 1) * 128 + 8 * c4) + (u & 1);
        dst[0] = qv.x; dst[2] = qv.y; dst[4] = qv.z; dst[6] = qv.w;
    }

    int k0 = c * CK;
    int j = tid;

    // S-phase: acc for 23 u-pairs in registers, K staged in two 32-dim chunks
    ull acc[23];
    #pragma unroll
    for (int i = 0; i < 23; i++) acc[i] = 0ull;

    #pragma unroll 1
    for (int cc = 0; cc < 2; cc++) {
        __syncthreads();
        for (int i = tid; i < CK * 8; i += K3T) {
            int row = i >> 3, dc = i & 7;
            kv4[row * 9 + dc] =
                k4g[((size_t)(b * Ll + k0 + row) * Hh + h) * 16 + cc * 8 + dc];
        }
        __syncthreads();
        #pragma unroll 1
        for (int dc = 0; dc < 8; dc++) {
            float4 kr = kv4[j * 9 + dc];
            ull kk0 = pack2(kr.x, kr.x);
            ull kk1 = pack2(kr.y, kr.y);
            ull kk2 = pack2(kr.z, kr.z);
            ull kk3 = pack2(kr.w, kr.w);
            int dcg = cc * 8 + dc;
            #pragma unroll
            for (int i = 0; i < 23; i++) {
                ulonglong2 qA = qsU[i * 32 + dcg * 2];
                ulonglong2 qB = qsU[i * 32 + dcg * 2 + 1];
                acc[i] = fma2(qA.x, kk0, acc[i]);
                acc[i] = fma2(qA.y, kk1, acc[i]);
                acc[i] = fma2(qB.x, kk2, acc[i]);
                acc[i] = fma2(qB.y, kk3, acc[i]);
            }
        }
    }
    #pragma unroll
    for (int i = 0; i < 23; i++) {
        float lo, hi;
        unpack2(acc[i], lo, hi);
        ss[(2 * i) * SST + j] = lo;
        if (2 * i + 1 < SSK) ss[(2 * i + 1) * SST + j] = hi;
    }
    __syncthreads();   // ss visible; kv buffer free

    // stage V chunk 0 NOW (overlaps with softmax; kv free since S-phase done)
    for (int i = tid; i < 128 * 16; i += K3T) {
        int row = i >> 4, c4 = i & 15;
        kv4[row * 17 + c4] =
            v4g[((size_t)(b * Ll + k0 + row) * Hh + h) * 16 + c4];
    }

    // partial softmax per row u (warp-per-row, 8 warps)
    int wid = tid >> 5, lane = tid & 31;
    for (int u = wid; u < SSK; u += 8) {
        float x[8];
        float mxv = -1e30f;
        #pragma unroll
        for (int t = 0; t < 8; t++) { x[t] = ss[u * SST + lane + t * 32]; mxv = fmaxf(mxv, x[t]); }
        #pragma unroll
        for (int o = 16; o; o >>= 1) mxv = fmaxf(mxv, __shfl_xor_sync(0xffffffffu, mxv, o));
        float sum = 0.f;
        #pragma unroll
        for (int t = 0; t < 8; t++) { float p = __expf(0.125f * (x[t] - mxv)); x[t] = p; sum += p; }
        #pragma unroll
        for (int o = 16; o; o >>= 1) sum += __shfl_xor_sync(0xffffffffu, sum, o);
        #pragma unroll
        for (int t = 0; t < 8; t++) ss[u * SST + lane + t * 32] = x[t];
        if (lane == 0) {
            g_pmax[(bh * NC + c) * SSK + u] = 0.125f * mxv;
            g_psum[(bh * NC + c) * SSK + u] = sum;
        }
    }
    __syncthreads();   // softmax ss + V0 staging both complete

    // P@V: thread = (ug, d4); ug<15 owns u = {3ug, 3ug+1, 3ug+2}
    int d4 = tid & 15, ug = tid >> 4;
    int u0 = ug * 3;
    ull a0l = 0, a0h = 0, a1l = 0, a1h = 0, a2l = 0, a2h = 0;

    #pragma unroll 1
    for (int vc = 0; vc < 2; vc++) {
        if (vc) {
            __syncthreads();   // PV pass 0 done reading kv
            for (int i = tid; i < 128 * 16; i += K3T) {
                int row = i >> 4, c4 = i & 15;
                kv4[row * 17 + c4] =
                    v4g[((size_t)(b * Ll + k0 + 128 + row) * Hh + h) * 16 + c4];
            }
            __syncthreads();
        }
        if (ug < 15) {
            #pragma unroll 4
            for (int jj = 0; jj < 128; jj++) {
                ulonglong2 vv = kvU[jj * 17 + d4];
                int jg = vc * 128 + jj;
                float p0 = ss[u0 * SST + jg];
                float p1 = ss[(u0 + 1) * SST + jg];
                float p2 = ss[(u0 + 2) * SST + jg];
                ull b0 = pack2(p0, p0), b1 = pack2(p1, p1), b2 = pack2(p2, p2);
                a0l = fma2(b0, vv.x, a0l);  a0h = fma2(b0, vv.y, a0h);
                a1l = fma2(b1, vv.x, a1l);  a1h = fma2(b1, vv.y, a1h);
                a2l = fma2(b2, vv.x, a2l);  a2h = fma2(b2, vv.y, a2h);
            }
        }
    }
    if (ug < 15) {
        ulonglong2* po = (ulonglong2*)g_pout;
        size_t baseo = ((size_t)(bh * NC + c) * SSK) * 16 + d4;
        po[baseo + (size_t)u0 * 16]       = make_ulonglong2(a0l, a0h);
        po[baseo + (size_t)(u0 + 1) * 16] = make_ulonglong2(a1l, a1h);
        po[baseo + (size_t)(u0 + 2) * 16] = make_ulonglong2(a2l, a2h);
    }

    // ---- fused combine: last CTA of this bh merges partials and scatters ----
    __threadfence();
    __syncthreads();
    __shared__ int s_last;
    if (tid == 0) s_last = (atomicAdd(&g_cnt[bh], 1) == NC - 1) ? 1 : 0;
    __syncthreads();
    if (!s_last) return;
    __threadfence();

    for (int i = tid; i < SSK * 16; i += K3T) {
        int u = i >> 4, dq = i & 15;
        float gm = -1e30f;
        #pragma unroll
        for (int cc = 0; cc < NC; cc++)
            gm = fmaxf(gm, g_pmax[(bh * NC + cc) * SSK + u]);
        float denom = 0.f;
        float4 a = make_float4(0.f, 0.f, 0.f, 0.f);
        #pragma unroll
        for (int cc = 0; cc < NC; cc++) {
            float w = __expf(g_pmax[(bh * NC + cc) * SSK + u] - gm);
            denom += g_psum[(bh * NC + cc) * SSK + u] * w;
            float4 po = g_pout[((bh * NC + cc) * SSK + u) * 16 + dq];
            a.x += w * po.x; a.y += w * po.y; a.z += w * po.z; a.w += w * po.w;
        }
        float inv = 1.0f / denom;
        a.x *= inv; a.y *= inv; a.z *= inv; a.w *= inv;
        int lsel = tops[u];
        out4[((size_t)(b * Ll + lsel) * Hh + h) * 16 + dq] = a;
    }
}

// ---------------- launch ----------------
extern "C" void kernel_launch(void* const* d_in, const int* in_sizes, int n_in,
                              void* d_out, int out_size) {
    const float4* q4 = (const float4*)d_in[0];
    const float4* k4 = (const float4*)d_in[1];
    const float4* v4 = (const float4*)d_in[2];
    const void* idxp = d_in[n_in - 1];
    for (int i = 0; i < n_in; i++)
        if (in_sizes[i] == Ll * SSK) idxp = d_in[i];
    float4* out4 = (float4*)d_out;

    cudaFuncSetAttribute(k3_attn, cudaFuncAttributeMaxDynamicSharedMemorySize, K3_SMEM);

    int n4 = out_size / 4;
    k0_zero<<<(n4 + 255) / 256, 256>>>(out4, n4, (const unsigned*)idxp);
    k1_score<<<Bb * Ll / 8, 256>>>(q4, k4, idxp);
    k2_topk<<<BH, 256>>>();
    k3_attn<<<dim3(NC, BH), K3T, K3_SMEM>>>(q4, k4, v4, out4);
}

// round 14
// speedup vs baseline: 2.2920x; 1.0118x over previous
#include <cuda_runtime.h>

// ProbAttention (Informer ProbSparse) for B=2, L=4096, H=8, D=64, sample_k = n_top = 45.

#define Bb   2
#define Ll   4096
#define Hh   8
#define Dd   64
#define SSK  45          // sample_k == n_top
#define BH   (Bb*Hh)     // 16
#define NC   16          // kv chunks in phase 3
#define CK   256         // keys per chunk in k3
#define SST  257         // padded ss row stride (floats)

typedef unsigned long long ull;

// ---- scratch (static device globals: no allocation allowed) ----
__device__ int    g_idx_is64;
__device__ float  g_M[BH * Ll];
__device__ int    g_top[BH * SSK];
__device__ float  g_pmax[BH * NC * SSK];
__device__ float  g_psum[BH * NC * SSK];
__device__ float4 g_pout[BH * NC * SSK * (Dd / 4)];
__device__ int    g_cnt[BH];             // k3 completion counters (reset each launch)

// ---- f32x2 packed-FMA helpers ----
__device__ __forceinline__ ull fma2(ull a, ull b, ull c) {
    ull d;
    asm("fma.rn.f32x2 %0, %1, %2, %3;" : "=l"(d) : "l"(a), "l"(b), "l"(c));
    return d;
}
__device__ __forceinline__ ull pack2(float x, float y) {
    ull r;
    asm("mov.b64 %0, {%1, %2};" : "=l"(r) : "f"(x), "f"(y));
    return r;
}
__device__ __forceinline__ void unpack2(ull v, float& x, float& y) {
    asm("mov.b64 {%0, %1}, %2;" : "=f"(x), "=f"(y) : "l"(v));
}

// ---------------- K0: zero output + detect index dtype + reset counters ----------------
__global__ void k0_zero(float4* __restrict__ out4, int n4,
                        const unsigned* __restrict__ idxsrc) {
    if (blockIdx.x == 0) {
        __shared__ int nz;
        if (threadIdx.x == 0) nz = 0;
        __syncthreads();
        if (threadIdx.x < 128) {
            unsigned v = idxsrc[threadIdx.x * 2 + 1];
            if (v != 0u) atomicAdd(&nz, 1);
        }
        __syncthreads();
        if (threadIdx.x == 0) g_idx_is64 = (nz == 0) ? 1 : 0;
        if (threadIdx.x < BH) g_cnt[threadIdx.x] = 0;
    }
    int i = blockIdx.x * 256 + threadIdx.x;
    if (i < n4) out4[i] = make_float4(0.f, 0.f, 0.f, 0.f);
}

// ---------------- K1: sampled scores M ----------------
// One warp per (b,l); 8 heads at once; fully coalesced 512B loads per step.
// 128-thread blocks (grid 2048) for ~14 CTAs/SM occupancy; index loads
// software-pipelined one iteration ahead to break the idx->gather chain.
__global__ __launch_bounds__(128) void k1_score(const float4* __restrict__ q4,
                                                const float4* __restrict__ k4,
                                                const void* __restrict__ idxsrc) {
    int w    = blockIdx.x * 4 + (threadIdx.x >> 5);
    int lane = threadIdx.x & 31;
    int b = w >> 12;
    int l = w & (Ll - 1);

    const float4* qp = q4 + (size_t)(b * Ll + l) * (Hh * Dd / 4);
    float4 qv[4];
    #pragma unroll
    for (int t = 0; t < 4; t++) qv[t] = qp[t * 32 + lane];

    float mx[4] = {-1e30f, -1e30f, -1e30f, -1e30f};
    float sm[4] = {0.f, 0.f, 0.f, 0.f};

    const int is64 = g_idx_is64;
    const long long* ip64 = (const long long*)idxsrc + (size_t)l * SSK;
    const int*       ip32 = (const int*)idxsrc + (size_t)l * SSK;

    int idx = is64 ? (int)ip64[0] : ip32[0];
    #pragma unroll 3
    for (int s = 0; s < SSK; s++) {
        int nidx = (s + 1 < SSK) ? (is64 ? (int)ip64[s + 1] : ip32[s + 1]) : 0;
        const float4* kp = k4 + (size_t)(b * Ll + idx) * (Hh * Dd / 4);
        #pragma unroll
        for (int t = 0; t < 4; t++) {
            float4 kv = kp[t * 32 + lane];
            float p = qv[t].x*kv.x + qv[t].y*kv.y + qv[t].z*kv.z + qv[t].w*kv.w;
            p += __shfl_xor_sync(0xffffffffu, p, 8);
            p += __shfl_xor_sync(0xffffffffu, p, 4);
            p += __shfl_xor_sync(0xffffffffu, p, 2);
            p += __shfl_xor_sync(0xffffffffu, p, 1);
            mx[t] = fmaxf(mx[t], p);
            sm[t] += p;
        }
        idx = nidx;
    }
    if ((lane & 15) == 0) {
        int half = lane >> 4;
        #pragma unroll
        for (int t = 0; t < 4; t++) {
            int h = 2 * t + half;
            g_M[(b * Hh + h) * Ll + l] = mx[t] - sm[t] * (1.0f / (float)Ll);
        }
    }
}

// ---------------- K2: top-45 per (b,h) via 4-round radix select ----------------
__global__ __launch_bounds__(256) void k2_topk() {
    int bh  = blockIdx.x;
    int tid = threadIdx.x;
    int wid = tid >> 5, lane = tid & 31;

    __shared__ unsigned hist[256];
    __shared__ unsigned warptot[8];
    __shared__ unsigned sh_pivot, sh_above;
    __shared__ int n_gt, n_eq;

    unsigned key[16];
    #pragma unroll
    for (int i = 0; i < 16; i++) {
        unsigned u = __float_as_uint(g_M[bh * Ll + i * 256 + tid]);
        key[i] = (u & 0x80000000u) ? ~u : (u | 0x80000000u);
    }

    unsigned prefix = 0, pmask = 0;
    int need = SSK;

    #pragma unroll
    for (int round = 0; round < 4; round++) {
        int shift = 24 - round * 8;
        hist[tid] = 0;
        if (tid == 0) { n_gt = 0; n_eq = 0; }
        __syncthreads();
        #pragma unroll
        for (int i = 0; i < 16; i++)
            if ((key[i] & pmask) == prefix)
                atomicAdd(&hist[(key[i] >> shift) & 255u], 1u);
        __syncthreads();

        unsigned x = hist[tid];
        unsigned s = x;
        #pragma unroll
        for (int o = 1; o < 32; o <<= 1) {
            unsigned y = __shfl_down_sync(0xffffffffu, s, o);
            if (lane + o < 32) s += y;
        }
        unsigned wt = __shfl_sync(0xffffffffu, s, 0);
        if (lane == 0) warptot[wid] = wt;
        __syncthreads();
        unsigned hs = 0;
        #pragma unroll
        for (int w2 = 0; w2 < 8; w2++)
            if (w2 > wid) hs += warptot[w2];
        unsigned S = s + hs;
        unsigned above = S - x;
        if ((int)S >= need && (int)above < need) {
            sh_pivot = (unsigned)tid;
            sh_above = above;
        }
        __syncthreads();
        prefix |= sh_pivot << shift;
        pmask  |= 0xffu << shift;
        need   -= (int)sh_above;
        __syncthreads();
    }

    int base = bh * SSK;
    #pragma unroll
    for (int i = 0; i < 16; i++)
        if (key[i] > prefix) {
            int p = atomicAdd(&n_gt, 1);
            g_top[base + p] = i * 256 + tid;
        }
    __syncthreads();
    int gt = n_gt;
    #pragma unroll
    for (int i = 0; i < 16; i++)
        if (key[i] == prefix) {
            int e = atomicAdd(&n_eq, 1);
            if (e < need) g_top[base + gt + e] = i * 256 + tid;
        }
}

// ---------------- K3: split-KV sparse attention + fused combine ----------------
#define K3T   256
#define QS2F  (23 * 128)
#define KVF   (CK * 9 * 4)
#define K3_SMEM ((QS2F + KVF + SSK * SST) * 4 + 256)

__global__ __launch_bounds__(K3T, 2) void k3_attn(const float4* __restrict__ q4,
                                                  const float4* __restrict__ k4g,
                                                  const float4* __restrict__ v4g,
                                                  float4* __restrict__ out4) {
    int c  = blockIdx.x;
    int bh = blockIdx.y;
    int b = bh >> 3, h = bh & 7;
    int tid = threadIdx.x;

    extern __shared__ float smem[];
    float* qs2f = smem;
    float* kv   = qs2f + QS2F;
    float* ss   = kv + KVF;
    int*   tops = (int*)(ss + SSK * SST);
    float4*           kv4 = (float4*)kv;
    const ulonglong2* kvU = (const ulonglong2*)kv;
    const ulonglong2* qsU = (const ulonglong2*)qs2f;

    if (tid < SSK) tops[tid] = g_top[bh * SSK + tid];
    __syncthreads();

    // stage Q in u-pair-packed layout
    for (int i = tid; i < 46 * 16; i += K3T) {
        int u = i >> 4, c4 = i & 15;
        float4 qv = (u < SSK)
            ? q4[((size_t)(b * Ll + tops[u]) * Hh + h) * (Dd / 4) + c4]
            : make_float4(0.f, 0.f, 0.f, 0.f);
        float* dst = qs2f + ((u >> 1) * 128 + 8 * c4) + (u & 1);
        dst[0] = qv.x; dst[2] = qv.y; dst[4] = qv.z; dst[6] = qv.w;
    }

    int k0 = c * CK;
    int j = tid;

    // S-phase: acc for 23 u-pairs in registers, K staged in two 32-dim chunks
    ull acc[23];
    #pragma unroll
    for (int i = 0; i < 23; i++) acc[i] = 0ull;

    #pragma unroll 1
    for (int cc = 0; cc < 2; cc++) {
        __syncthreads();
        for (int i = tid; i < CK * 8; i += K3T) {
            int row = i >> 3, dc = i & 7;
            kv4[row * 9 + dc] =
                k4g[((size_t)(b * Ll + k0 + row) * Hh + h) * 16 + cc * 8 + dc];
        }
        __syncthreads();
        #pragma unroll 1
        for (int dc = 0; dc < 8; dc++) {
            float4 kr = kv4[j * 9 + dc];
            ull kk0 = pack2(kr.x, kr.x);
            ull kk1 = pack2(kr.y, kr.y);
            ull kk2 = pack2(kr.z, kr.z);
            ull kk3 = pack2(kr.w, kr.w);
            int dcg = cc * 8 + dc;
            #pragma unroll
            for (int i = 0; i < 23; i++) {
                ulonglong2 qA = qsU[i * 32 + dcg * 2];
                ulonglong2 qB = qsU[i * 32 + dcg * 2 + 1];
                acc[i] = fma2(qA.x, kk0, acc[i]);
                acc[i] = fma2(qA.y, kk1, acc[i]);
                acc[i] = fma2(qB.x, kk2, acc[i]);
                acc[i] = fma2(qB.y, kk3, acc[i]);
            }
        }
    }
    #pragma unroll
    for (int i = 0; i < 23; i++) {
        float lo, hi;
        unpack2(acc[i], lo, hi);
        ss[(2 * i) * SST + j] = lo;
        if (2 * i + 1 < SSK) ss[(2 * i + 1) * SST + j] = hi;
    }
    __syncthreads();   // ss visible; kv buffer free

    // stage V chunk 0 NOW (overlaps with softmax; kv free since S-phase done)
    for (int i = tid; i < 128 * 16; i += K3T) {
        int row = i >> 4, c4 = i & 15;
        kv4[row * 17 + c4] =
            v4g[((size_t)(b * Ll + k0 + row) * Hh + h) * 16 + c4];
    }

    // partial softmax per row u (warp-per-row, 8 warps)
    int wid = tid >> 5, lane = tid & 31;
    for (int u = wid; u < SSK; u += 8) {
        float x[8];
        float mxv = -1e30f;
        #pragma unroll
        for (int t = 0; t < 8; t++) { x[t] = ss[u * SST + lane + t * 32]; mxv = fmaxf(mxv, x[t]); }
        #pragma unroll
        for (int o = 16; o; o >>= 1) mxv = fmaxf(mxv, __shfl_xor_sync(0xffffffffu, mxv, o));
        float sum = 0.f;
        #pragma unroll
        for (int t = 0; t < 8; t++) { float p = __expf(0.125f * (x[t] - mxv)); x[t] = p; sum += p; }
        #pragma unroll
        for (int o = 16; o; o >>= 1) sum += __shfl_xor_sync(0xffffffffu, sum, o);
        #pragma unroll
        for (int t = 0; t < 8; t++) ss[u * SST + lane + t * 32] = x[t];
        if (lane == 0) {
            g_pmax[(bh * NC + c) * SSK + u] = 0.125f * mxv;
            g_psum[(bh * NC + c) * SSK + u] = sum;
        }
    }
    __syncthreads();   // softmax ss + V0 staging both complete

    // P@V: thread = (ug, d4); ug<15 owns u = {3ug, 3ug+1, 3ug+2}
    int d4 = tid & 15, ug = tid >> 4;
    int u0 = ug * 3;
    ull a0l = 0, a0h = 0, a1l = 0, a1h = 0, a2l = 0, a2h = 0;

    #pragma unroll 1
    for (int vc = 0; vc < 2; vc++) {
        if (vc) {
            __syncthreads();   // PV pass 0 done reading kv
            for (int i = tid; i < 128 * 16; i += K3T) {
                int row = i >> 4, c4 = i & 15;
                kv4[row * 17 + c4] =
                    v4g[((size_t)(b * Ll + k0 + 128 + row) * Hh + h) * 16 + c4];
            }
            __syncthreads();
        }
        if (ug < 15) {
            #pragma unroll 4
            for (int jj = 0; jj < 128; jj++) {
                ulonglong2 vv = kvU[jj * 17 + d4];
                int jg = vc * 128 + jj;
                float p0 = ss[u0 * SST + jg];
                float p1 = ss[(u0 + 1) * SST + jg];
                float p2 = ss[(u0 + 2) * SST + jg];
                ull b0 = pack2(p0, p0), b1 = pack2(p1, p1), b2 = pack2(p2, p2);
                a0l = fma2(b0, vv.x, a0l);  a0h = fma2(b0, vv.y, a0h);
                a1l = fma2(b1, vv.x, a1l);  a1h = fma2(b1, vv.y, a1h);
                a2l = fma2(b2, vv.x, a2l);  a2h = fma2(b2, vv.y, a2h);
            }
        }
    }
    if (ug < 15) {
        ulonglong2* po = (ulonglong2*)g_pout;
        size_t baseo = ((size_t)(bh * NC + c) * SSK) * 16 + d4;
        po[baseo + (size_t)u0 * 16]       = make_ulonglong2(a0l, a0h);
        po[baseo + (size_t)(u0 + 1) * 16] = make_ulonglong2(a1l, a1h);
        po[baseo + (size_t)(u0 + 2) * 16] = make_ulonglong2(a2l, a2h);
    }

    // ---- fused combine: last CTA of this bh merges partials and scatters ----
    __threadfence();
    __syncthreads();
    __shared__ int s_last;
    if (tid == 0) s_last = (atomicAdd(&g_cnt[bh], 1) == NC - 1) ? 1 : 0;
    __syncthreads();
    if (!s_last) return;
    __threadfence();

    for (int i = tid; i < SSK * 16; i += K3T) {
        int u = i >> 4, dq = i & 15;
        float gm = -1e30f;
        #pragma unroll
        for (int cc = 0; cc < NC; cc++)
            gm = fmaxf(gm, g_pmax[(bh * NC + cc) * SSK + u]);
        float denom = 0.f;
        float4 a = make_float4(0.f, 0.f, 0.f, 0.f);
        #pragma unroll
        for (int cc = 0; cc < NC; cc++) {
            float w = __expf(g_pmax[(bh * NC + cc) * SSK + u] - gm);
            denom += g_psum[(bh * NC + cc) * SSK + u] * w;
            float4 po = g_pout[((bh * NC + cc) * SSK + u) * 16 + dq];
            a.x += w * po.x; a.y += w * po.y; a.z += w * po.z; a.w += w * po.w;
        }
        float inv = 1.0f / denom;
        a.x *= inv; a.y *= inv; a.z *= inv; a.w *= inv;
        int lsel = tops[u];
        out4[((size_t)(b * Ll + lsel) * Hh + h) * 16 + dq] = a;
    }
}

// ---------------- launch ----------------
extern "C" void kernel_launch(void* const* d_in, const int* in_sizes, int n_in,
                              void* d_out, int out_size) {
    const float4* q4 = (const float4*)d_in[0];
    const float4* k4 = (const float4*)d_in[1];
    const float4* v4 = (const float4*)d_in[2];
    const void* idxp = d_in[n_in - 1];
    for (int i = 0; i < n_in; i++)
        if (in_sizes[i] == Ll * SSK) idxp = d_in[i];
    float4* out4 = (float4*)d_out;

    cudaFuncSetAttribute(k3_attn, cudaFuncAttributeMaxDynamicSharedMemorySize, K3_SMEM);

    int n4 = out_size / 4;
    k0_zero<<<(n4 + 255) / 256, 256>>>(out4, n4, (const unsigned*)idxp);
    k1_score<<<Bb * Ll / 4, 128>>>(q4, k4, idxp);
    k2_topk<<<BH, 256>>>();
    k3_attn<<<dim3(NC, BH), K3T, K3_SMEM>>>(q4, k4, v4, out4);
}